// round 3
// baseline (speedup 1.0000x reference)
#include <cuda_runtime.h>
#include <cstdint>

// Problem constants
#define NB 32      // batch
#define TT 512     // time steps
#define DD 512     // input dim
#define HH 1024    // hidden dim
#define GG 3072    // 3*H

#define NCTA 128   // persistent grid
#define NTHR 256

// Scratch (module-load allocated; no runtime alloc)
__device__ float g_gates[(size_t)NB * TT * GG];  // 16384 x 3072
__device__ float g_zr[NB * 2 * HH];              // 32 x 2048
__device__ unsigned char g_reset[NB * TT];       // canonicalized reset flags

// Monotonic grid barrier state (zeroed by epilogue kernel each launch)
__device__ unsigned g_cnt = 0;
__device__ unsigned g_release = 0;

// ---------------------------------------------------------------------------
// Prep: detect reset dtype (bool8 vs int32) and canonicalize to uchar.
// int32 0/1 data has ALL bytes at offset %4!=0 equal to zero; dense random
// bool8 data cannot (prob ~2^-3072 over 4096 bytes).
// ---------------------------------------------------------------------------
__global__ void prep_reset(const unsigned char* __restrict__ raw)
{
    __shared__ int s_bool8;
    int tid = threadIdx.x;
    if (tid == 0) s_bool8 = 0;
    __syncthreads();
    for (int i = tid; i < 4096; i += blockDim.x) {
        if ((i & 3) != 0 && raw[i] != 0) s_bool8 = 1;
    }
    __syncthreads();
    bool is_bool8 = (s_bool8 != 0);
    if (is_bool8) {
        for (int i = tid; i < NB * TT; i += blockDim.x)
            g_reset[i] = (raw[i] != 0);
    } else {
        const int* r32 = (const int*)raw;
        for (int i = tid; i < NB * TT; i += blockDim.x)
            g_reset[i] = (r32[i] != 0);
    }
}

// ---------------------------------------------------------------------------
// GEMM: gates = X(16384x512) @ Wi(512x3072) + bias
// ---------------------------------------------------------------------------
__global__ __launch_bounds__(256) void gemm_gates(
    const float* __restrict__ X, const float* __restrict__ Wi,
    const float* __restrict__ bias)
{
    const int K = DD;
    const int Nn = GG;

    __shared__ float As[8][128];
    __shared__ float Bs[8][128];

    const int bm = blockIdx.y * 128;
    const int bn = blockIdx.x * 128;
    const int tid = threadIdx.x;

    const int aRow = tid >> 1;
    const int aCol = (tid & 1) << 2;
    const int bRow = tid >> 5;
    const int bCol = (tid & 31) << 2;

    const int tRow = (tid >> 4) << 3;
    const int tCol = (tid & 15) << 3;

    float acc[8][8];
#pragma unroll
    for (int i = 0; i < 8; i++)
#pragma unroll
        for (int j = 0; j < 8; j++) acc[i][j] = 0.0f;

    for (int k0 = 0; k0 < K; k0 += 8) {
        float4 a4 = *reinterpret_cast<const float4*>(
            X + (size_t)(bm + aRow) * K + k0 + aCol);
        As[aCol + 0][aRow] = a4.x;
        As[aCol + 1][aRow] = a4.y;
        As[aCol + 2][aRow] = a4.z;
        As[aCol + 3][aRow] = a4.w;
        *reinterpret_cast<float4*>(&Bs[bRow][bCol]) =
            *reinterpret_cast<const float4*>(Wi + (size_t)(k0 + bRow) * Nn + bn + bCol);
        __syncthreads();

#pragma unroll
        for (int kk = 0; kk < 8; kk++) {
            float4 a0 = *reinterpret_cast<const float4*>(&As[kk][tRow]);
            float4 a1 = *reinterpret_cast<const float4*>(&As[kk][tRow + 4]);
            float4 b0 = *reinterpret_cast<const float4*>(&Bs[kk][tCol]);
            float4 b1 = *reinterpret_cast<const float4*>(&Bs[kk][tCol + 4]);
            float ar[8] = {a0.x, a0.y, a0.z, a0.w, a1.x, a1.y, a1.z, a1.w};
            float br[8] = {b0.x, b0.y, b0.z, b0.w, b1.x, b1.y, b1.z, b1.w};
#pragma unroll
            for (int i = 0; i < 8; i++)
#pragma unroll
                for (int j = 0; j < 8; j++) acc[i][j] += ar[i] * br[j];
        }
        __syncthreads();
    }

#pragma unroll
    for (int i = 0; i < 8; i++) {
#pragma unroll
        for (int j = 0; j < 8; j += 4) {
            float4 v;
            v.x = acc[i][j + 0] + bias[bn + tCol + j + 0];
            v.y = acc[i][j + 1] + bias[bn + tCol + j + 1];
            v.z = acc[i][j + 2] + bias[bn + tCol + j + 2];
            v.w = acc[i][j + 3] + bias[bn + tCol + j + 3];
            *reinterpret_cast<float4*>(
                g_gates + (size_t)(bm + tRow + i) * Nn + bn + tCol + j) = v;
        }
    }
}

// ---------------------------------------------------------------------------
// Monotonic epoch grid barrier. n is the 1-based barrier index within this
// launch; g_cnt/g_release only grow during the kernel (epilogue resets them).
// ---------------------------------------------------------------------------
__device__ __forceinline__ void grid_barrier(unsigned n)
{
    __syncthreads();
    if (threadIdx.x == 0) {
        __threadfence();
        unsigned old = atomicAdd(&g_cnt, 1u);
        if (old == n * NCTA - 1) {
            atomicExch(&g_release, n);
        } else {
            while (*(volatile unsigned*)&g_release < n) { __nanosleep(32); }
        }
        __threadfence();
    }
    __syncthreads();
}

extern __shared__ float dsm[];

// ---------------------------------------------------------------------------
// Persistent recurrence kernel
// 128 CTAs x 256 threads. CTA x owns zr cols [x*16, x*16+16) and a-cols
// [x*8, x*8+8), for all 32 batches.
// Dynamic smem: w_s[24][1024] floats (96KB) + h4_s[256*32] float4 (128KB)
// ---------------------------------------------------------------------------
__global__ __launch_bounds__(NTHR, 1) void gru_persistent(
    const float* __restrict__ w_h, const float* __restrict__ h0,
    float* out0, float* __restrict__ out1)
{
    float* w_s = dsm;                               // 24*1024 floats
    float4* h4_s = (float4*)(dsm + 24 * 1024);      // 256*32 float4

    const int x = blockIdx.x;
    const int tid = threadIdx.x;
    const int lane = tid & 31;      // batch
    const int wp = tid >> 5;        // warp 0..7

    // ---- one-time weight preload (transposed into w_s[c][k]) ----
    for (int i = tid; i < 24 * 1024; i += NTHR) {
        int c = i % 24;
        int k = i / 24;
        int gcol = (c < 16) ? (x * 16 + c) : (2048 + x * 8 + (c - 16));
        w_s[c * 1024 + k] = w_h[(size_t)k * GG + gcol];
    }
    __syncthreads();

    const float4* h0_4 = (const float4*)h0;
    const float4* out0_4c = (const float4*)out0;
    const float4* zr4 = (const float4*)g_zr;

    unsigned nbar = 0;

    for (int t = 0; t < TT; t++) {
        // ---- stage h_eff for all 32 batches into h4_s (swizzled) ----
        for (int i = tid; i < 8192; i += NTHR) {
            int b = i >> 8;
            int k4 = i & 255;
            float4 v;
            if (t == 0 || g_reset[b * TT + t] != 0)
                v = h0_4[k4];
            else
                v = out0_4c[((size_t)b * TT + (t - 1)) * 256 + k4];
            h4_s[(k4 << 5) + (b ^ (k4 & 31))] = v;
        }
        __syncthreads();

        // ---- phase 1: zr = sigmoid(gx + h @ Wzr), 2 cols per warp ----
        {
            const float4* wA = (const float4*)(w_s + (2 * wp) * 1024);
            const float4* wB = (const float4*)(w_s + (2 * wp + 1) * 1024);
            float aA0 = 0.f, aA1 = 0.f, aB0 = 0.f, aB1 = 0.f;
#pragma unroll 4
            for (int k4 = 0; k4 < 256; ++k4) {
                float4 h = h4_s[(k4 << 5) + (lane ^ (k4 & 31))];
                float4 va = wA[k4];
                float4 vb = wB[k4];
                aA0 = fmaf(h.x, va.x, aA0); aA1 = fmaf(h.y, va.y, aA1);
                aA0 = fmaf(h.z, va.z, aA0); aA1 = fmaf(h.w, va.w, aA1);
                aB0 = fmaf(h.x, vb.x, aB0); aB1 = fmaf(h.y, vb.y, aB1);
                aB0 = fmaf(h.z, vb.z, aB0); aB1 = fmaf(h.w, vb.w, aB1);
            }
            int jA = x * 16 + 2 * wp;       // global zr col
            size_t grow = ((size_t)lane * TT + t) * GG;
            float vA = g_gates[grow + jA] + (aA0 + aA1);
            float vB = g_gates[grow + jA + 1] + (aB0 + aB1);
            g_zr[lane * (2 * HH) + jA]     = 1.0f / (1.0f + expf(-vA));
            g_zr[lane * (2 * HH) + jA + 1] = 1.0f / (1.0f + expf(-vB));
        }

        grid_barrier(++nbar);

        // ---- phase 2 pre-read: h_eff at this thread's own a-cols ----
        float hkA = 0.f, hkB = 0.f;
        int jA = x * 8 + 2 * wp;            // only meaningful for wp<4
        if (wp < 4) {
            int k4a = jA >> 2, ca = jA & 3;
            int k4b = (jA + 1) >> 2, cb = (jA + 1) & 3;
            hkA = ((const float*)&h4_s[(k4a << 5) + (lane ^ (k4a & 31))])[ca];
            hkB = ((const float*)&h4_s[(k4b << 5) + (lane ^ (k4b & 31))])[cb];
        }
        __syncthreads();

        // ---- stage rh = r * h in place ----
        for (int i = tid; i < 8192; i += NTHR) {
            int b = i >> 8;
            int k4 = i & 255;
            int sidx = (k4 << 5) + (b ^ (k4 & 31));
            float4 h = h4_s[sidx];
            float4 r = zr4[b * 512 + 256 + k4];  // r part (offset 1024 floats)
            h.x *= r.x; h.y *= r.y; h.z *= r.z; h.w *= r.w;
            h4_s[sidx] = h;
        }
        __syncthreads();

        // ---- phase 2: a = tanh(gx_a + rh @ Wa); update; store ----
        if (wp < 4) {
            const float4* wA = (const float4*)(w_s + (16 + 2 * wp) * 1024);
            const float4* wB = (const float4*)(w_s + (16 + 2 * wp + 1) * 1024);
            float aA0 = 0.f, aA1 = 0.f, aB0 = 0.f, aB1 = 0.f;
#pragma unroll 4
            for (int k4 = 0; k4 < 256; ++k4) {
                float4 h = h4_s[(k4 << 5) + (lane ^ (k4 & 31))];
                float4 va = wA[k4];
                float4 vb = wB[k4];
                aA0 = fmaf(h.x, va.x, aA0); aA1 = fmaf(h.y, va.y, aA1);
                aA0 = fmaf(h.z, va.z, aA0); aA1 = fmaf(h.w, va.w, aA1);
                aB0 = fmaf(h.x, vb.x, aB0); aB1 = fmaf(h.y, vb.y, aB1);
                aB0 = fmaf(h.z, vb.z, aB0); aB1 = fmaf(h.w, vb.w, aB1);
            }
            size_t grow = ((size_t)lane * TT + t) * GG;
            float vA = g_gates[grow + 2 * HH + jA] + (aA0 + aA1);
            float vB = g_gates[grow + 2 * HH + jA + 1] + (aB0 + aB1);
            float aAv = tanhf(vA);
            float aBv = tanhf(vB);
            float zA = g_zr[lane * (2 * HH) + jA];
            float zB = g_zr[lane * (2 * HH) + jA + 1];
            float hnA = (1.0f - zA) * hkA + zA * aAv;
            float hnB = (1.0f - zB) * hkB + zB * aBv;
            size_t o = ((size_t)lane * TT + t) * HH + jA;
            out0[o] = hnA;
            out0[o + 1] = hnB;
            out1[o] = hnA;
            out1[o + 1] = hnB;
        }

        grid_barrier(++nbar);
    }
}

// ---------------------------------------------------------------------------
// Epilogue: write third output and reset barrier state for the next replay.
// Runs after gru_persistent in stream order.
// ---------------------------------------------------------------------------
__global__ void epilogue(const float* __restrict__ h0, float* __restrict__ dst)
{
    int i = blockIdx.x * blockDim.x + threadIdx.x;
    if (i < HH) dst[i] = h0[i];
    if (i == 0) { g_cnt = 0; g_release = 0; }
}

// ---------------------------------------------------------------------------
extern "C" void kernel_launch(void* const* d_in, const int* in_sizes, int n_in,
                              void* d_out, int out_size)
{
    const float* x = (const float*)d_in[0];
    const unsigned char* reset_raw = (const unsigned char*)d_in[1];
    const float* w_i = (const float*)d_in[2];
    const float* w_h = (const float*)d_in[3];
    const float* b = (const float*)d_in[4];
    const float* h0 = (const float*)d_in[5];

    float* out0 = (float*)d_out;
    float* out1 = out0 + (size_t)NB * TT * HH;
    float* outh = out1 + (size_t)NB * TT * HH;

    static const size_t SMEM = 24 * 1024 * 4 + 256 * 32 * 16;  // 229376
    cudaFuncSetAttribute(gru_persistent,
                         cudaFuncAttributeMaxDynamicSharedMemorySize, (int)SMEM);

    // 0) canonicalize reset flags (dtype-agnostic)
    prep_reset<<<1, 256>>>(reset_raw);

    // 1) gates = x @ w_i + b
    {
        dim3 grid(GG / 128, (NB * TT) / 128);
        gemm_gates<<<grid, 256>>>(x, w_i, b);
    }

    // 2) full recurrence in ONE persistent kernel
    gru_persistent<<<NCTA, NTHR, SMEM>>>(w_h, h0, out0, out1);

    // 3) third output + barrier state reset
    epilogue<<<1, HH>>>(h0, outh);
}

// round 4
// speedup vs baseline: 1.0389x; 1.0389x over previous
#include <cuda_runtime.h>
#include <cstdint>

// Problem constants
#define NB 32      // batch
#define TT 512     // time steps
#define DD 512     // input dim
#define HH 1024    // hidden dim
#define GG 3072    // 3*H

#define NCTA 128   // persistent grid
#define NTHR 256

#define WPAD 1028  // padded column stride (floats) for weight smem

// Scratch (module-load allocated; no runtime alloc)
__device__ float g_gates[(size_t)NB * TT * GG];  // 16384 x 3072
__device__ float g_zr[NB * 2 * HH];              // 32 x 2048
__device__ unsigned char g_reset[NB * TT];       // canonicalized reset flags

// Monotonic grid barrier state (zeroed by epilogue kernel each launch)
__device__ unsigned g_cnt = 0;
__device__ unsigned g_release = 0;

// packed f32x2 fma: acc = a*b + acc (each u64 = 2 packed floats)
#define FMA2(acc, a, b) \
    asm("fma.rn.f32x2 %0, %1, %2, %0;" : "+l"(acc) : "l"(a), "l"(b))

// ---------------------------------------------------------------------------
// Prep: detect reset dtype (bool8 vs int32) and canonicalize to uchar.
// ---------------------------------------------------------------------------
__global__ void prep_reset(const unsigned char* __restrict__ raw)
{
    __shared__ int s_bool8;
    int tid = threadIdx.x;
    if (tid == 0) s_bool8 = 0;
    __syncthreads();
    for (int i = tid; i < 4096; i += blockDim.x) {
        if ((i & 3) != 0 && raw[i] != 0) s_bool8 = 1;
    }
    __syncthreads();
    bool is_bool8 = (s_bool8 != 0);
    if (is_bool8) {
        for (int i = tid; i < NB * TT; i += blockDim.x)
            g_reset[i] = (raw[i] != 0);
    } else {
        const int* r32 = (const int*)raw;
        for (int i = tid; i < NB * TT; i += blockDim.x)
            g_reset[i] = (r32[i] != 0);
    }
}

// ---------------------------------------------------------------------------
// GEMM: gates = X(16384x512) @ Wi(512x3072) + bias  (unchanged; proven)
// ---------------------------------------------------------------------------
__global__ __launch_bounds__(256) void gemm_gates(
    const float* __restrict__ X, const float* __restrict__ Wi,
    const float* __restrict__ bias)
{
    const int K = DD;
    const int Nn = GG;

    __shared__ float As[8][128];
    __shared__ float Bs[8][128];

    const int bm = blockIdx.y * 128;
    const int bn = blockIdx.x * 128;
    const int tid = threadIdx.x;

    const int aRow = tid >> 1;
    const int aCol = (tid & 1) << 2;
    const int bRow = tid >> 5;
    const int bCol = (tid & 31) << 2;

    const int tRow = (tid >> 4) << 3;
    const int tCol = (tid & 15) << 3;

    float acc[8][8];
#pragma unroll
    for (int i = 0; i < 8; i++)
#pragma unroll
        for (int j = 0; j < 8; j++) acc[i][j] = 0.0f;

    for (int k0 = 0; k0 < K; k0 += 8) {
        float4 a4 = *reinterpret_cast<const float4*>(
            X + (size_t)(bm + aRow) * K + k0 + aCol);
        As[aCol + 0][aRow] = a4.x;
        As[aCol + 1][aRow] = a4.y;
        As[aCol + 2][aRow] = a4.z;
        As[aCol + 3][aRow] = a4.w;
        *reinterpret_cast<float4*>(&Bs[bRow][bCol]) =
            *reinterpret_cast<const float4*>(Wi + (size_t)(k0 + bRow) * Nn + bn + bCol);
        __syncthreads();

#pragma unroll
        for (int kk = 0; kk < 8; kk++) {
            float4 a0 = *reinterpret_cast<const float4*>(&As[kk][tRow]);
            float4 a1 = *reinterpret_cast<const float4*>(&As[kk][tRow + 4]);
            float4 b0 = *reinterpret_cast<const float4*>(&Bs[kk][tCol]);
            float4 b1 = *reinterpret_cast<const float4*>(&Bs[kk][tCol + 4]);
            float ar[8] = {a0.x, a0.y, a0.z, a0.w, a1.x, a1.y, a1.z, a1.w};
            float br[8] = {b0.x, b0.y, b0.z, b0.w, b1.x, b1.y, b1.z, b1.w};
#pragma unroll
            for (int i = 0; i < 8; i++)
#pragma unroll
                for (int j = 0; j < 8; j++) acc[i][j] += ar[i] * br[j];
        }
        __syncthreads();
    }

#pragma unroll
    for (int i = 0; i < 8; i++) {
#pragma unroll
        for (int j = 0; j < 8; j += 4) {
            float4 v;
            v.x = acc[i][j + 0] + bias[bn + tCol + j + 0];
            v.y = acc[i][j + 1] + bias[bn + tCol + j + 1];
            v.z = acc[i][j + 2] + bias[bn + tCol + j + 2];
            v.w = acc[i][j + 3] + bias[bn + tCol + j + 3];
            *reinterpret_cast<float4*>(
                g_gates + (size_t)(bm + tRow + i) * Nn + bn + tCol + j) = v;
        }
    }
}

// ---------------------------------------------------------------------------
// Monotonic epoch grid barrier.
// ---------------------------------------------------------------------------
__device__ __forceinline__ void grid_barrier(unsigned n)
{
    __threadfence();
    __syncthreads();
    if (threadIdx.x == 0) {
        unsigned old = atomicAdd(&g_cnt, 1u);
        if (old == n * NCTA - 1) {
            atomicExch(&g_release, n);
        } else {
            while (*(volatile unsigned*)&g_release < n) { __nanosleep(16); }
        }
        __threadfence();
    }
    __syncthreads();
}

extern __shared__ float dsm[];

// ---------------------------------------------------------------------------
// Persistent recurrence kernel (v2: packed f32x2, 4 cols/thread, k-split warps)
// CTA x owns zr cols [16x,16x+16) and a cols [8x,8x+8), all 32 batches.
// smem: w_s 24 cols x 1028 floats (98688B, padded stride) +
//       hp4 8192 float4 (h, swizzled [b][k4^b]) (131072B) +
//       red2 256 float2 (2048B)  => 231808 B total
// ---------------------------------------------------------------------------
__global__ __launch_bounds__(NTHR, 1) void gru_persistent(
    const float* __restrict__ w_h, const float* __restrict__ h0,
    float* out0, float* __restrict__ out1)
{
    float* w_s = dsm;                                   // 24*WPAD floats
    float4* hp4 = (float4*)(dsm + 24 * WPAD);           // 8192 float4
    float2* red2 = (float2*)(dsm + 24 * WPAD + 32768);  // 256 float2

    const int x = blockIdx.x;
    const int tid = threadIdx.x;
    const int lane = tid & 31;
    const int wp = tid >> 5;
    const int cs = lane >> 4;       // 0/1: column sub-group
    const int bl = lane & 15;       // batch within half

    // phase1 coords: warp = (bh, cg, kh); thread covers 4 cols x 1 batch x 512k
    const int p1_bh = wp & 1;
    const int p1_cg = (wp >> 1) & 1;
    const int p1_kh = wp >> 2;
    const int p1_b  = p1_bh * 16 + bl;
    const int p1_c0 = p1_cg * 8 + cs * 4;       // local zr col 0..12
    const int p1_k4 = p1_kh * 128;

    // phase2 coords: warp = (kq, bh); thread covers 4 cols x 1 batch x 256k
    const int p2_kq = wp >> 1;
    const int p2_bh = wp & 1;
    const int p2_b  = p2_bh * 16 + bl;
    const int p2_c0 = cs * 4;                   // local a col 0..4
    const int p2_k4 = p2_kq * 64;

    // ---- one-time weight preload: w_s[c*WPAD + k] ----
    for (int i = tid; i < 24 * 1024; i += NTHR) {
        int c = i % 24;
        int k = i / 24;
        int gcol = (c < 16) ? (x * 16 + c) : (2048 + x * 8 + (c - 16));
        w_s[c * WPAD + k] = w_h[(size_t)k * GG + gcol];
    }
    __syncthreads();

    const float4* h0_4 = (const float4*)h0;
    const float4* out0_4 = (const float4*)out0;
    const float4* gates4 = (const float4*)g_gates;
    const float4* gzr4 = (const float4*)g_zr;
    float4* gzr4w = (float4*)g_zr;
    const ulonglong2* hu2 = (const ulonglong2*)hp4;

    unsigned nbar = 0;

    for (int t = 0; t < TT; t++) {
        // ---- prefetch phase1 gates (kh==0 finalizers) ----
        float4 gx1;
        if (p1_kh == 0)
            gx1 = gates4[((size_t)p1_b * TT + t) * 768 + x * 4 + p1_cg * 2 + cs];

        // ---- stage h_eff for all batches into hp4 (swizzled [b][k4^b]) ----
        for (int i = tid; i < 8192; i += NTHR) {
            int b = i >> 8;
            int k4 = i & 255;
            float4 v;
            if (t == 0 || g_reset[b * TT + t] != 0)
                v = h0_4[k4];
            else
                v = __ldcg(&out0_4[((size_t)b * TT + (t - 1)) * 256 + k4]);
            hp4[b * 256 + (k4 ^ b)] = v;
        }
        __syncthreads();

        // ---- phase1 compute: 4 cols, packed f32x2 over k ----
        {
            unsigned long long acc[4] = {0ull, 0ull, 0ull, 0ull};
            const ulonglong2* hrow = hu2 + p1_b * 256;
            const ulonglong2* w0 = (const ulonglong2*)(w_s + (p1_c0 + 0) * WPAD);
            const ulonglong2* w1 = (const ulonglong2*)(w_s + (p1_c0 + 1) * WPAD);
            const ulonglong2* w2 = (const ulonglong2*)(w_s + (p1_c0 + 2) * WPAD);
            const ulonglong2* w3 = (const ulonglong2*)(w_s + (p1_c0 + 3) * WPAD);
#pragma unroll 4
            for (int k4 = p1_k4; k4 < p1_k4 + 128; ++k4) {
                ulonglong2 hv = hrow[k4 ^ p1_b];
                ulonglong2 v0 = w0[k4];
                ulonglong2 v1 = w1[k4];
                ulonglong2 v2 = w2[k4];
                ulonglong2 v3 = w3[k4];
                FMA2(acc[0], hv.x, v0.x); FMA2(acc[0], hv.y, v0.y);
                FMA2(acc[1], hv.x, v1.x); FMA2(acc[1], hv.y, v1.y);
                FMA2(acc[2], hv.x, v2.x); FMA2(acc[2], hv.y, v2.y);
                FMA2(acc[3], hv.x, v3.x); FMA2(acc[3], hv.y, v3.y);
            }
            // ---- 2-way k reduction + sigmoid, two rounds (cg groups) ----
#pragma unroll
            for (int r = 0; r < 2; r++) {
                if (p1_kh == 1 && p1_cg == r) {
#pragma unroll
                    for (int q = 0; q < 4; q++)
                        red2[(cs * 4 + q) * 32 + p1_b] =
                            *reinterpret_cast<float2*>(&acc[q]);
                }
                __syncthreads();
                if (p1_kh == 0 && p1_cg == r) {
                    float s[4];
#pragma unroll
                    for (int q = 0; q < 4; q++) {
                        float2 pq = red2[(cs * 4 + q) * 32 + p1_b];
                        float2 aq = *reinterpret_cast<float2*>(&acc[q]);
                        s[q] = (aq.x + aq.y) + (pq.x + pq.y);
                    }
                    float4 o;
                    o.x = 1.0f / (1.0f + __expf(-(gx1.x + s[0])));
                    o.y = 1.0f / (1.0f + __expf(-(gx1.y + s[1])));
                    o.z = 1.0f / (1.0f + __expf(-(gx1.z + s[2])));
                    o.w = 1.0f / (1.0f + __expf(-(gx1.w + s[3])));
                    gzr4w[p1_b * 512 + x * 4 + p1_cg * 2 + cs] = o;
                }
                __syncthreads();
            }
        }

        grid_barrier(++nbar);

        // ---- phase2 prefetch + pre-read raw h at own a-cols (kq==0) ----
        float4 gx2, z4, hown;
        if (p2_kq == 0) {
            gx2 = gates4[((size_t)p2_b * TT + t) * 768 + 512 + x * 2 + cs];
            z4 = __ldcg(&gzr4[p2_b * 512 + x * 2 + cs]);   // z cols [0,1024)
            int k4h = x * 2 + cs;
            hown = hp4[p2_b * 256 + (k4h ^ p2_b)];
        }
        __syncthreads();

        // ---- stage rh = r * h in place ----
        for (int i = tid; i < 8192; i += NTHR) {
            int b = i >> 8;
            int k4 = i & 255;
            int sidx = b * 256 + (k4 ^ b);
            float4 h = hp4[sidx];
            float4 r = __ldcg(&gzr4[b * 512 + 256 + k4]);  // r cols [1024,2048)
            h.x *= r.x; h.y *= r.y; h.z *= r.z; h.w *= r.w;
            hp4[sidx] = h;
        }
        __syncthreads();

        // ---- phase2 compute: 4 a-cols, packed f32x2 ----
        {
            unsigned long long acc[4] = {0ull, 0ull, 0ull, 0ull};
            const ulonglong2* hrow = hu2 + p2_b * 256;
            const ulonglong2* w0 = (const ulonglong2*)(w_s + (16 + p2_c0 + 0) * WPAD);
            const ulonglong2* w1 = (const ulonglong2*)(w_s + (16 + p2_c0 + 1) * WPAD);
            const ulonglong2* w2 = (const ulonglong2*)(w_s + (16 + p2_c0 + 2) * WPAD);
            const ulonglong2* w3 = (const ulonglong2*)(w_s + (16 + p2_c0 + 3) * WPAD);
#pragma unroll 4
            for (int k4 = p2_k4; k4 < p2_k4 + 64; ++k4) {
                ulonglong2 hv = hrow[k4 ^ p2_b];
                ulonglong2 v0 = w0[k4];
                ulonglong2 v1 = w1[k4];
                ulonglong2 v2 = w2[k4];
                ulonglong2 v3 = w3[k4];
                FMA2(acc[0], hv.x, v0.x); FMA2(acc[0], hv.y, v0.y);
                FMA2(acc[1], hv.x, v1.x); FMA2(acc[1], hv.y, v1.y);
                FMA2(acc[2], hv.x, v2.x); FMA2(acc[2], hv.y, v2.y);
                FMA2(acc[3], hv.x, v3.x); FMA2(acc[3], hv.y, v3.y);
            }
            // ---- 4-way k reduction: rounds r=1..3 fold into kq==0 ----
#pragma unroll
            for (int r = 1; r < 4; r++) {
                if (p2_kq == r) {
#pragma unroll
                    for (int q = 0; q < 4; q++)
                        red2[(cs * 4 + q) * 32 + p2_b] =
                            *reinterpret_cast<float2*>(&acc[q]);
                }
                __syncthreads();
                if (p2_kq == 0) {
#pragma unroll
                    for (int q = 0; q < 4; q++) {
                        float2 pq = red2[(cs * 4 + q) * 32 + p2_b];
                        float2* aq = reinterpret_cast<float2*>(&acc[q]);
                        aq->x += pq.x; aq->y += pq.y;
                    }
                }
                __syncthreads();
            }
            if (p2_kq == 0) {
                float s[4];
#pragma unroll
                for (int q = 0; q < 4; q++) {
                    float2 aq = *reinterpret_cast<float2*>(&acc[q]);
                    s[q] = aq.x + aq.y;
                }
                float aV[4];
                aV[0] = tanhf(gx2.x + s[0]);
                aV[1] = tanhf(gx2.y + s[1]);
                aV[2] = tanhf(gx2.z + s[2]);
                aV[3] = tanhf(gx2.w + s[3]);
                float4 hn;
                hn.x = (1.0f - z4.x) * hown.x + z4.x * aV[0];
                hn.y = (1.0f - z4.y) * hown.y + z4.y * aV[1];
                hn.z = (1.0f - z4.z) * hown.z + z4.z * aV[2];
                hn.w = (1.0f - z4.w) * hown.w + z4.w * aV[3];
                size_t o4 = ((size_t)p2_b * TT + t) * 256 + x * 2 + cs;
                ((float4*)out0)[o4] = hn;
                ((float4*)out1)[o4] = hn;
            }
        }

        grid_barrier(++nbar);
    }
}

// ---------------------------------------------------------------------------
// Epilogue: third output + reset barrier state for next replay.
// ---------------------------------------------------------------------------
__global__ void epilogue(const float* __restrict__ h0, float* __restrict__ dst)
{
    int i = blockIdx.x * blockDim.x + threadIdx.x;
    if (i < HH) dst[i] = h0[i];
    if (i == 0) { g_cnt = 0; g_release = 0; }
}

// ---------------------------------------------------------------------------
extern "C" void kernel_launch(void* const* d_in, const int* in_sizes, int n_in,
                              void* d_out, int out_size)
{
    const float* x = (const float*)d_in[0];
    const unsigned char* reset_raw = (const unsigned char*)d_in[1];
    const float* w_i = (const float*)d_in[2];
    const float* w_h = (const float*)d_in[3];
    const float* b = (const float*)d_in[4];
    const float* h0 = (const float*)d_in[5];

    float* out0 = (float*)d_out;
    float* out1 = out0 + (size_t)NB * TT * HH;
    float* outh = out1 + (size_t)NB * TT * HH;

    // smem: 24*WPAD*4 + 8192*16 + 256*8 = 98688 + 131072 + 2048 = 231808
    static const size_t SMEM = 24 * WPAD * 4 + 8192 * 16 + 256 * 8;
    cudaFuncSetAttribute(gru_persistent,
                         cudaFuncAttributeMaxDynamicSharedMemorySize, (int)SMEM);

    // 0) canonicalize reset flags
    prep_reset<<<1, 256>>>(reset_raw);

    // 1) gates = x @ w_i + b
    {
        dim3 grid(GG / 128, (NB * TT) / 128);
        gemm_gates<<<grid, 256>>>(x, w_i, b);
    }

    // 2) full recurrence in ONE persistent kernel
    gru_persistent<<<NCTA, NTHR, SMEM>>>(w_h, h0, out0, out1);

    // 3) third output + barrier state reset
    epilogue<<<1, HH>>>(h0, outh);
}

// round 5
// speedup vs baseline: 1.3150x; 1.2658x over previous
#include <cuda_runtime.h>
#include <cstdint>

// Problem constants
#define NB 32      // batch
#define TT 512     // time steps
#define DD 512     // input dim
#define HH 1024    // hidden dim
#define GG 3072    // 3*H

#define NCTA 128   // persistent grid
#define NTHR 256

// Scratch (module-load allocated; no runtime alloc)
__device__ float g_gates[(size_t)NB * TT * GG];  // 16384 x 3072
__device__ float g_zr[NB * 2 * HH];              // 32 x 2048
__device__ unsigned g_rmask[TT];                 // per-step reset bitmasks

// Hierarchical barrier state (zeroed by epilogue BEFORE gru each replay)
__device__ unsigned g_leaf[16];
__device__ unsigned g_root;
__device__ unsigned g_release;

// packed f32x2 fma: acc = a*b + acc (each u64 = 2 packed floats)
#define FMA2(acc, a, b) \
    asm("fma.rn.f32x2 %0, %1, %2, %0;" : "+l"(acc) : "l"(a), "l"(b))

__device__ __forceinline__ unsigned long long dup2(float v)
{
    unsigned long long r;
    asm("mov.b64 %0, {%1, %1};" : "=l"(r) : "f"(v));
    return r;
}

// ---------------------------------------------------------------------------
// Prep: detect reset dtype (bool8 vs int32), build per-step bitmasks.
// ---------------------------------------------------------------------------
__global__ void prep_reset(const unsigned char* __restrict__ raw)
{
    __shared__ int s_bool8;
    int tid = threadIdx.x;
    if (tid == 0) s_bool8 = 0;
    __syncthreads();
    for (int i = tid; i < 4096; i += blockDim.x)
        if ((i & 3) != 0 && raw[i] != 0) s_bool8 = 1;
    __syncthreads();
    bool b8 = (s_bool8 != 0);
    const int* r32 = (const int*)raw;
    for (int t = tid; t < TT; t += blockDim.x) {
        unsigned m = 0;
        for (int b = 0; b < NB; b++) {
            bool rv = b8 ? (raw[b * TT + t] != 0) : (r32[b * TT + t] != 0);
            if (rv) m |= (1u << b);
        }
        if (t == 0) m = 0xFFFFFFFFu;
        g_rmask[t] = m;
    }
}

// ---------------------------------------------------------------------------
// GEMM: gates = X(16384x512) @ Wi(512x3072) + bias   (f32x2 micro-kernel)
// ---------------------------------------------------------------------------
__global__ __launch_bounds__(256) void gemm_gates(
    const float* __restrict__ X, const float* __restrict__ Wi,
    const float* __restrict__ bias)
{
    const int K = DD;
    const int Nn = GG;

    __shared__ float As[8][128];
    __shared__ float Bs[8][128];

    const int bm = blockIdx.y * 128;
    const int bn = blockIdx.x * 128;
    const int tid = threadIdx.x;

    const int aRow = tid >> 1;
    const int aCol = (tid & 1) << 2;
    const int bRow = tid >> 5;
    const int bCol = (tid & 31) << 2;

    const int tRow = (tid >> 4) << 3;
    const int tCol = (tid & 15) << 3;

    unsigned long long acc2[8][4];
#pragma unroll
    for (int i = 0; i < 8; i++)
#pragma unroll
        for (int j = 0; j < 4; j++) acc2[i][j] = 0ull;

    for (int k0 = 0; k0 < K; k0 += 8) {
        float4 a4 = *reinterpret_cast<const float4*>(
            X + (size_t)(bm + aRow) * K + k0 + aCol);
        As[aCol + 0][aRow] = a4.x;
        As[aCol + 1][aRow] = a4.y;
        As[aCol + 2][aRow] = a4.z;
        As[aCol + 3][aRow] = a4.w;
        *reinterpret_cast<float4*>(&Bs[bRow][bCol]) =
            *reinterpret_cast<const float4*>(Wi + (size_t)(k0 + bRow) * Nn + bn + bCol);
        __syncthreads();

#pragma unroll
        for (int kk = 0; kk < 8; kk++) {
            float4 a0 = *reinterpret_cast<const float4*>(&As[kk][tRow]);
            float4 a1 = *reinterpret_cast<const float4*>(&As[kk][tRow + 4]);
            ulonglong2 b01 = *reinterpret_cast<const ulonglong2*>(&Bs[kk][tCol]);
            ulonglong2 b23 = *reinterpret_cast<const ulonglong2*>(&Bs[kk][tCol + 4]);
            float ar[8] = {a0.x, a0.y, a0.z, a0.w, a1.x, a1.y, a1.z, a1.w};
#pragma unroll
            for (int i = 0; i < 8; i++) {
                unsigned long long aa = dup2(ar[i]);
                FMA2(acc2[i][0], aa, b01.x);
                FMA2(acc2[i][1], aa, b01.y);
                FMA2(acc2[i][2], aa, b23.x);
                FMA2(acc2[i][3], aa, b23.y);
            }
        }
        __syncthreads();
    }

#pragma unroll
    for (int i = 0; i < 8; i++) {
#pragma unroll
        for (int j2 = 0; j2 < 4; j2 += 2) {
            unsigned long long v0 = acc2[i][j2];
            unsigned long long v1 = acc2[i][j2 + 1];
            float2 p0 = *reinterpret_cast<float2*>(&v0);
            float2 p1 = *reinterpret_cast<float2*>(&v1);
            int j = j2 * 2;
            float4 v;
            v.x = p0.x + bias[bn + tCol + j + 0];
            v.y = p0.y + bias[bn + tCol + j + 1];
            v.z = p1.x + bias[bn + tCol + j + 2];
            v.w = p1.y + bias[bn + tCol + j + 3];
            *reinterpret_cast<float4*>(
                g_gates + (size_t)(bm + tRow + i) * Nn + bn + tCol + j) = v;
        }
    }
}

extern __shared__ float dsm[];

// ---------------------------------------------------------------------------
// Persistent recurrence kernel (v3: hierarchical barrier, overlap, lean syncs)
// smem: w_s 24x1024 floats (96KB) + hp4 8192 float4 (128KB) + red 768 floats
// ---------------------------------------------------------------------------
__global__ __launch_bounds__(NTHR, 1) void gru_persistent(
    const float* __restrict__ w_h, const float* __restrict__ h0,
    float* out0, float* __restrict__ out1)
{
    float* w_s = dsm;                              // 24*1024 floats
    float4* hp4 = (float4*)(dsm + 24 * 1024);      // 8192 float4
    float* red = dsm + 24 * 1024 + 32768;          // 768 floats

    const int x = blockIdx.x;
    const int tid = threadIdx.x;
    const int lane = tid & 31;
    const int wp = tid >> 5;
    const int cs = lane >> 4;
    const int bl = lane & 15;
    const int leaf = x & 15;

    // phase1: warp = (bh, cg, kh); thread = 4 cols x 1 batch x 512 k
    const int p1_bh = wp & 1;
    const int p1_cg = (wp >> 1) & 1;
    const int p1_kh = wp >> 2;
    const int p1_b  = p1_bh * 16 + bl;
    const int p1_c0 = p1_cg * 8 + cs * 4;
    const int p1_k4 = p1_kh * 128;

    // phase2: warp = (kq, bh); thread = 4 cols x 1 batch x 256 k
    const int p2_kq = wp >> 1;
    const int p2_bh = wp & 1;
    const int p2_b  = p2_bh * 16 + bl;
    const int p2_c0 = cs * 4;
    const int p2_k4 = p2_kq * 64;

    // ---- one-time weight preload: w_s[c*1024 + k] ----
    for (int i = tid; i < 24 * 1024; i += NTHR) {
        int c = i % 24;
        int k = i / 24;
        int gcol = (c < 16) ? (x * 16 + c) : (2048 + x * 8 + (c - 16));
        w_s[c * 1024 + k] = w_h[(size_t)k * GG + gcol];
    }
    __syncthreads();

    const float4* h0_4 = (const float4*)h0;
    const float4* out0_4 = (const float4*)out0;
    const float4* gates4 = (const float4*)g_gates;
    const float4* gzr4 = (const float4*)g_zr;
    float4* gzr4w = (float4*)g_zr;
    const ulonglong2* hu2 = (const ulonglong2*)hp4;

    for (int t = 0; t < TT; t++) {
        // ---- independent prefetches (overlap with barrier-2 wait) ----
        float4 gx1;
        if (p1_kh == 0)
            gx1 = gates4[((size_t)p1_b * TT + t) * 768 + x * 4 + p1_cg * 2 + cs];
        unsigned rm = g_rmask[t];
        int tp = (t > 0) ? (t - 1) : 0;

        // ---- wait for barrier 2 of previous step (h(t-1) ready) ----
        if (t > 0) {
            unsigned n = 2u * t;
            if (tid == 0) {
                while (*(volatile unsigned*)&g_release < n) __nanosleep(32);
                __threadfence();
            }
            __syncthreads();
        }

        // ---- stage h_eff (all 32 batches) into hp4, swizzled ----
#pragma unroll 4
        for (int b = 0; b < 32; b++) {
            float4 v;
            if ((rm >> b) & 1u)
                v = h0_4[tid];
            else
                v = __ldcg(&out0_4[((size_t)b * TT + tp) * 256 + tid]);
            hp4[b * 256 + (tid ^ b)] = v;
        }
        __syncthreads();

        // ---- phase1 FMA: 4 zr-cols, packed f32x2, half-k per warp ----
        {
            unsigned long long acc[4] = {0ull, 0ull, 0ull, 0ull};
            const ulonglong2* hrow = hu2 + p1_b * 256;
            const ulonglong2* w0 = (const ulonglong2*)(w_s + (p1_c0 + 0) * 1024);
            const ulonglong2* w1 = (const ulonglong2*)(w_s + (p1_c0 + 1) * 1024);
            const ulonglong2* w2 = (const ulonglong2*)(w_s + (p1_c0 + 2) * 1024);
            const ulonglong2* w3 = (const ulonglong2*)(w_s + (p1_c0 + 3) * 1024);
#pragma unroll 4
            for (int k4 = p1_k4; k4 < p1_k4 + 128; ++k4) {
                ulonglong2 hv = hrow[k4 ^ p1_b];
                ulonglong2 v0 = w0[k4];
                ulonglong2 v1 = w1[k4];
                ulonglong2 v2 = w2[k4];
                ulonglong2 v3 = w3[k4];
                FMA2(acc[0], hv.x, v0.x); FMA2(acc[0], hv.y, v0.y);
                FMA2(acc[1], hv.x, v1.x); FMA2(acc[1], hv.y, v1.y);
                FMA2(acc[2], hv.x, v2.x); FMA2(acc[2], hv.y, v2.y);
                FMA2(acc[3], hv.x, v3.x); FMA2(acc[3], hv.y, v3.y);
            }
            if (p1_kh == 1) {
#pragma unroll
                for (int q = 0; q < 4; q++) {
                    float2 a2 = *reinterpret_cast<float2*>(&acc[q]);
                    red[(p1_cg * 8 + cs * 4 + q) * 32 + p1_b] = a2.x + a2.y;
                }
            }
            __syncthreads();
            if (p1_kh == 0) {
                float s[4];
#pragma unroll
                for (int q = 0; q < 4; q++) {
                    float2 a2 = *reinterpret_cast<float2*>(&acc[q]);
                    s[q] = (a2.x + a2.y) + red[(p1_cg * 8 + cs * 4 + q) * 32 + p1_b];
                }
                float4 o;
                o.x = 1.0f / (1.0f + __expf(-(gx1.x + s[0])));
                o.y = 1.0f / (1.0f + __expf(-(gx1.y + s[1])));
                o.z = 1.0f / (1.0f + __expf(-(gx1.z + s[2])));
                o.w = 1.0f / (1.0f + __expf(-(gx1.w + s[3])));
                gzr4w[p1_b * 512 + x * 4 + p1_cg * 2 + cs] = o;
            }
        }

        // ---- barrier 1 arrive (zr ready) ----
        unsigned n1 = 2u * t + 1u;
        __syncthreads();
        if (tid == 0) {
            __threadfence();
            unsigned o = atomicAdd(&g_leaf[leaf], 1u);
            if (o == n1 * 8u - 1u) {
                unsigned o2 = atomicAdd(&g_root, 1u);
                if (o2 == n1 * 16u - 1u) atomicExch(&g_release, n1);
            }
        }

        // ---- overlap: prefetch local data while waiting ----
        float4 gx2, hown;
        if (p2_kq == 0) {
            gx2 = gates4[((size_t)p2_b * TT + t) * 768 + 512 + x * 2 + cs];
            int k4h = x * 2 + cs;
            hown = hp4[p2_b * 256 + (k4h ^ p2_b)];
        }

        // ---- barrier 1 wait ----
        if (tid == 0) {
            while (*(volatile unsigned*)&g_release < n1) __nanosleep(32);
            __threadfence();
        }
        __syncthreads();

        float4 z4;
        if (p2_kq == 0)
            z4 = __ldcg(&gzr4[p2_b * 512 + x * 2 + cs]);

        // ---- stage rh = r * h in place ----
#pragma unroll 4
        for (int b = 0; b < 32; b++) {
            int sidx = b * 256 + (tid ^ b);
            float4 h = hp4[sidx];
            float4 r = __ldcg(&gzr4[b * 512 + 256 + tid]);
            h.x *= r.x; h.y *= r.y; h.z *= r.z; h.w *= r.w;
            hp4[sidx] = h;
        }
        __syncthreads();

        // ---- phase2 FMA: 4 a-cols, packed f32x2, quarter-k per warp ----
        {
            unsigned long long acc[4] = {0ull, 0ull, 0ull, 0ull};
            const ulonglong2* hrow = hu2 + p2_b * 256;
            const ulonglong2* w0 = (const ulonglong2*)(w_s + (16 + p2_c0 + 0) * 1024);
            const ulonglong2* w1 = (const ulonglong2*)(w_s + (16 + p2_c0 + 1) * 1024);
            const ulonglong2* w2 = (const ulonglong2*)(w_s + (16 + p2_c0 + 2) * 1024);
            const ulonglong2* w3 = (const ulonglong2*)(w_s + (16 + p2_c0 + 3) * 1024);
#pragma unroll 4
            for (int k4 = p2_k4; k4 < p2_k4 + 64; ++k4) {
                ulonglong2 hv = hrow[k4 ^ p2_b];
                ulonglong2 v0 = w0[k4];
                ulonglong2 v1 = w1[k4];
                ulonglong2 v2 = w2[k4];
                ulonglong2 v3 = w3[k4];
                FMA2(acc[0], hv.x, v0.x); FMA2(acc[0], hv.y, v0.y);
                FMA2(acc[1], hv.x, v1.x); FMA2(acc[1], hv.y, v1.y);
                FMA2(acc[2], hv.x, v2.x); FMA2(acc[2], hv.y, v2.y);
                FMA2(acc[3], hv.x, v3.x); FMA2(acc[3], hv.y, v3.y);
            }
            if (p2_kq != 0) {
#pragma unroll
                for (int q = 0; q < 4; q++) {
                    float2 a2 = *reinterpret_cast<float2*>(&acc[q]);
                    red[((p2_kq - 1) * 8 + cs * 4 + q) * 32 + p2_b] = a2.x + a2.y;
                }
            }
            __syncthreads();
            if (p2_kq == 0) {
                float s[4];
#pragma unroll
                for (int q = 0; q < 4; q++) {
                    float2 a2 = *reinterpret_cast<float2*>(&acc[q]);
                    s[q] = (a2.x + a2.y)
                         + red[(0 * 8 + cs * 4 + q) * 32 + p2_b]
                         + red[(1 * 8 + cs * 4 + q) * 32 + p2_b]
                         + red[(2 * 8 + cs * 4 + q) * 32 + p2_b];
                }
                float aV0 = tanhf(gx2.x + s[0]);
                float aV1 = tanhf(gx2.y + s[1]);
                float aV2 = tanhf(gx2.z + s[2]);
                float aV3 = tanhf(gx2.w + s[3]);
                float4 hn;
                hn.x = (1.0f - z4.x) * hown.x + z4.x * aV0;
                hn.y = (1.0f - z4.y) * hown.y + z4.y * aV1;
                hn.z = (1.0f - z4.z) * hown.z + z4.z * aV2;
                hn.w = (1.0f - z4.w) * hown.w + z4.w * aV3;
                size_t o4 = ((size_t)p2_b * TT + t) * 256 + x * 2 + cs;
                ((float4*)out0)[o4] = hn;
                ((float4*)out1)[o4] = hn;
            }
        }

        // ---- barrier 2 arrive (h(t) ready); wait happens at next loop top ----
        unsigned n2 = 2u * t + 2u;
        __syncthreads();
        if (tid == 0) {
            __threadfence();
            unsigned o = atomicAdd(&g_leaf[leaf], 1u);
            if (o == n2 * 8u - 1u) {
                unsigned o2 = atomicAdd(&g_root, 1u);
                if (o2 == n2 * 16u - 1u) atomicExch(&g_release, n2);
            }
        }
    }
}

// ---------------------------------------------------------------------------
// Epilogue: runs BEFORE gru each replay — zero barrier state + write outh.
// ---------------------------------------------------------------------------
__global__ void epilogue(const float* __restrict__ h0, float* __restrict__ dst)
{
    int i = blockIdx.x * blockDim.x + threadIdx.x;
    if (i < HH) dst[i] = h0[i];
    if (i < 16) g_leaf[i] = 0;
    if (i == 16) g_root = 0;
    if (i == 17) g_release = 0;
}

// ---------------------------------------------------------------------------
extern "C" void kernel_launch(void* const* d_in, const int* in_sizes, int n_in,
                              void* d_out, int out_size)
{
    const float* x = (const float*)d_in[0];
    const unsigned char* reset_raw = (const unsigned char*)d_in[1];
    const float* w_i = (const float*)d_in[2];
    const float* w_h = (const float*)d_in[3];
    const float* b = (const float*)d_in[4];
    const float* h0 = (const float*)d_in[5];

    float* out0 = (float*)d_out;
    float* out1 = out0 + (size_t)NB * TT * HH;
    float* outh = out1 + (size_t)NB * TT * HH;

    // smem: 98304 + 131072 + 3072 = 232448 (= 227 KB max opt-in)
    static const size_t SMEM = 24 * 1024 * 4 + 8192 * 16 + 768 * 4;
    cudaFuncSetAttribute(gru_persistent,
                         cudaFuncAttributeMaxDynamicSharedMemorySize, (int)SMEM);

    // 0) reset masks
    prep_reset<<<1, 512>>>(reset_raw);

    // 1) gates = x @ w_i + b
    {
        dim3 grid(GG / 128, (NB * TT) / 128);
        gemm_gates<<<grid, 256>>>(x, w_i, b);
    }

    // 2) barrier state reset + third output (safe before recurrence)
    epilogue<<<1, 1024>>>(h0, outh);

    // 3) full recurrence in ONE persistent kernel (last launch -> ncu slot)
    gru_persistent<<<NCTA, NTHR, SMEM>>>(w_h, h0, out0, out1);
}